// round 1
// baseline (speedup 1.0000x reference)
#include <cuda_runtime.h>
#include <math.h>

// ---------------------------------------------------------------------------
// Problem constants
// ---------------------------------------------------------------------------
#define BATCH      8192
#define IN_DIM     2048
#define OUT_DIM    1000
#define DEPTH      10
#define NUM_INNER  1023     // 2^10 - 1
#define NUM_LEAF   1024     // 2^10
#define ALLPP_COLS 2047     // 1+2+...+1024

// d_out layout (floats): logits | mu | penalty | all_pp
#define LOGITS_OFF 0
#define MU_OFF     (BATCH * OUT_DIM)                    // 8,192,000
#define PEN_OFF    (MU_OFF + BATCH * NUM_LEAF)          // 16,580,608
#define ALLPP_OFF  (PEN_OFF + 1)                        // 16,580,609

// ---------------------------------------------------------------------------
// Scratch (static device globals; allocation-free)
// ---------------------------------------------------------------------------
__device__ float g_P[BATCH * 1024];          // sigmoid outputs, padded ld=1024 (32 MB)
__device__ float g_Wt[IN_DIM * 1024];        // W_inner[:,1:] transposed, padded to 1024 cols (8 MB)
__device__ float g_Wlt[1024 * 1024];         // W_leaf transposed, padded (4 MB)
__device__ float g_bias[1024];
__device__ float g_num[1024];
__device__ float g_den[1024];

// ---------------------------------------------------------------------------
// Prep kernels
// ---------------------------------------------------------------------------
__global__ void zero_acc_kernel() {
    int t = threadIdx.x;
    g_num[t] = 0.f;
    g_den[t] = 0.f;
}

// Wt[k][n] = W_inner[n][k+1] (n<1023 else 0); bias[n] = W_inner[n][0]
__global__ void prep_winner_kernel(const float* __restrict__ Wi) {
    int idx = blockIdx.x * blockDim.x + threadIdx.x;   // over 2048*1024
    if (idx >= IN_DIM * 1024) return;
    int k = idx >> 10;
    int n = idx & 1023;
    float v = 0.f;
    if (n < NUM_INNER) v = Wi[(size_t)n * (IN_DIM + 1) + 1 + k];
    g_Wt[(size_t)k * 1024 + n] = v;
    if (k == 0) g_bias[n] = (n < NUM_INNER) ? Wi[(size_t)n * (IN_DIM + 1)] : 0.f;
}

// Wlt[k][n] = W_leaf[n][k] (n<1000 else 0)
__global__ void prep_wleaf_kernel(const float* __restrict__ Wl) {
    int idx = blockIdx.x * blockDim.x + threadIdx.x;   // over 1024*1024
    if (idx >= 1024 * 1024) return;
    int k = idx >> 10;
    int n = idx & 1023;
    float v = 0.f;
    if (n < OUT_DIM) v = Wl[(size_t)n * NUM_LEAF + k];
    g_Wlt[(size_t)k * 1024 + n] = v;
}

// ---------------------------------------------------------------------------
// SGEMM: C[M, N_store] = A[M,K] (row-major, lda=K) * B[K, ldb] (row-major)
// 128x128x16 tiles, 256 threads, 8x8 per thread. Optional bias+sigmoid.
// M must be a multiple of 128. Tile N-extent = 128*gridDim.x must cover ldb.
// ---------------------------------------------------------------------------
#define BM 128
#define BN 128
#define BK 16

template <bool SIG>
__global__ __launch_bounds__(256, 2)
void sgemm_kernel(const float* __restrict__ A, const float* __restrict__ B,
                  float* __restrict__ C, int M, int N_store, int K,
                  int ldb, int ldc)
{
    __shared__ float As[BK][BM];
    __shared__ float Bs[BK][BN];

    const int tid = threadIdx.x;
    const int tx = tid & 15;
    const int ty = tid >> 4;
    const int bm = blockIdx.y * BM;
    const int bn = blockIdx.x * BN;

    float acc[8][8];
#pragma unroll
    for (int i = 0; i < 8; i++)
#pragma unroll
        for (int j = 0; j < 8; j++) acc[i][j] = 0.f;

    for (int k0 = 0; k0 < K; k0 += BK) {
        // A tile: 128 rows x 16 k-cols = 512 float4
#pragma unroll
        for (int i = 0; i < 2; i++) {
            int id  = tid + i * 256;
            int row = id >> 2;
            int c4  = (id & 3) << 2;
            float4 v = *(const float4*)&A[(size_t)(bm + row) * K + k0 + c4];
            As[c4 + 0][row] = v.x;
            As[c4 + 1][row] = v.y;
            As[c4 + 2][row] = v.z;
            As[c4 + 3][row] = v.w;
        }
        // B tile: 16 k-rows x 128 cols = 512 float4
#pragma unroll
        for (int i = 0; i < 2; i++) {
            int id = tid + i * 256;
            int kr = id >> 5;
            int c4 = (id & 31) << 2;
            *(float4*)&Bs[kr][c4] =
                *(const float4*)&B[(size_t)(k0 + kr) * ldb + bn + c4];
        }
        __syncthreads();

#pragma unroll
        for (int kk = 0; kk < BK; kk++) {
            float ra[8], rb[8];
#pragma unroll
            for (int i = 0; i < 8; i++) ra[i] = As[kk][ty * 8 + i];
#pragma unroll
            for (int j = 0; j < 8; j++) rb[j] = Bs[kk][tx * 8 + j];
#pragma unroll
            for (int i = 0; i < 8; i++)
#pragma unroll
                for (int j = 0; j < 8; j++) acc[i][j] += ra[i] * rb[j];
        }
        __syncthreads();
    }

#pragma unroll
    for (int i = 0; i < 8; i++) {
        int row = bm + ty * 8 + i;
#pragma unroll
        for (int j = 0; j < 8; j++) {
            int col = bn + tx * 8 + j;
            if (col < N_store) {
                float v = acc[i][j];
                if (SIG) {
                    v += g_bias[col];
                    v = 1.f / (1.f + __expf(-v));
                }
                C[(size_t)row * ldc + col] = v;
            }
        }
    }
}

// ---------------------------------------------------------------------------
// Tree cascade: per-row path probabilities for all levels.
// 2 rows/block, 256 threads. Writes all_pp (2047 cols/row) and final mu.
// ---------------------------------------------------------------------------
__global__ __launch_bounds__(256)
void cascade_kernel(const float* __restrict__ P, float* __restrict__ mu_out,
                    float* __restrict__ allpp)
{
    const int ROWS = 2;
    __shared__ float p_sh[ROWS][1024];
    __shared__ float buf[2][ROWS][1024];

    const int tid = threadIdx.x;
    const int b0 = blockIdx.x * ROWS;

#pragma unroll
    for (int r = 0; r < ROWS; r++)
        for (int j = tid; j < NUM_INNER; j += 256)
            p_sh[r][j] = P[(size_t)(b0 + r) * 1024 + j];

    if (tid < ROWS) {
        buf[0][tid][0] = 1.f;
        allpp[(size_t)(b0 + tid) * ALLPP_COLS + 0] = 1.f;
    }
    __syncthreads();

    int cur = 0;
    for (int lvl = 0; lvl < DEPTH; lvl++) {
        const int n = 1 << lvl;
        const int start = n - 1;
        const int outbase = 2 * n - 1;
        const int total = ROWS * 2 * n;
        for (int idx = tid; idx < total; idx += 256) {
            int r  = idx / (2 * n);
            int jj = idx - r * (2 * n);
            int j  = jj >> 1;
            int c  = jj & 1;
            float pm = p_sh[r][start + j];
            float v  = buf[cur][r][j] * (c ? pm : (1.f - pm));
            buf[cur ^ 1][r][jj] = v;
            allpp[(size_t)(b0 + r) * ALLPP_COLS + outbase + jj] = v;
            if (lvl == DEPTH - 1)
                mu_out[(size_t)(b0 + r) * NUM_LEAF + jj] = v;
        }
        __syncthreads();
        cur ^= 1;
    }
}

// ---------------------------------------------------------------------------
// Penalty: per-inner-node column sums of p*mu and mu over the batch.
// Node k (0..1022) pairs with all_pp column k. 64 blocks x 128 rows each.
// ---------------------------------------------------------------------------
__global__ __launch_bounds__(256)
void pen_accum_kernel(const float* __restrict__ P, const float* __restrict__ allpp)
{
    __shared__ float s_num[NUM_INNER];
    __shared__ float s_den[NUM_INNER];
    const int tid = threadIdx.x;
    for (int k = tid; k < NUM_INNER; k += 256) { s_num[k] = 0.f; s_den[k] = 0.f; }
    __syncthreads();

    const int rows_per_block = BATCH / gridDim.x;
    const int b0 = blockIdx.x * rows_per_block;
    for (int b = b0; b < b0 + rows_per_block; b++) {
        const float* mu_row = allpp + (size_t)b * ALLPP_COLS;
        const float* p_row  = P + (size_t)b * 1024;
        for (int k = tid; k < NUM_INNER; k += 256) {
            float m = mu_row[k];
            s_num[k] += p_row[k] * m;
            s_den[k] += m;
        }
    }
    __syncthreads();
    for (int k = tid; k < NUM_INNER; k += 256) {
        atomicAdd(&g_num[k], s_num[k]);
        atomicAdd(&g_den[k], s_den[k]);
    }
}

__global__ __launch_bounds__(256)
void pen_final_kernel(float* __restrict__ pen_out)
{
    __shared__ float red[256];
    const int tid = threadIdx.x;
    float local = 0.f;
    for (int k = tid; k < NUM_INNER; k += 256) {
        float alpha = g_num[k] / g_den[k];
        float pen = logf(alpha) + logf(1.f - alpha);
        if (!isfinite(pen)) pen = 0.f;
        int lvl = 31 - __clz(k + 1);
        float w = ldexpf(0.5f, -lvl);   // 0.5 * 2^-lvl
        local -= w * pen;
    }
    red[tid] = local;
    __syncthreads();
    for (int s = 128; s > 0; s >>= 1) {
        if (tid < s) red[tid] += red[tid + s];
        __syncthreads();
    }
    if (tid == 0) pen_out[0] = red[0];
}

// ---------------------------------------------------------------------------
// Launch
// ---------------------------------------------------------------------------
extern "C" void kernel_launch(void* const* d_in, const int* in_sizes, int n_in,
                              void* d_out, int out_size)
{
    const float* X  = (const float*)d_in[0];
    const float* Wi = (const float*)d_in[1];
    const float* Wl = (const float*)d_in[2];
    float* out = (float*)d_out;

    float* logits = out + LOGITS_OFF;
    float* mu     = out + MU_OFF;
    float* pen    = out + PEN_OFF;
    float* allpp  = out + ALLPP_OFF;

    float* P   = nullptr;
    float* Wt  = nullptr;
    float* Wlt = nullptr;
    cudaGetSymbolAddress((void**)&P,   g_P);
    cudaGetSymbolAddress((void**)&Wt,  g_Wt);
    cudaGetSymbolAddress((void**)&Wlt, g_Wlt);

    zero_acc_kernel<<<1, 1024>>>();
    prep_winner_kernel<<<(IN_DIM * 1024 + 255) / 256, 256>>>(Wi);
    prep_wleaf_kernel<<<(1024 * 1024 + 255) / 256, 256>>>(Wl);

    // GEMM1: P = sigmoid(bias + X @ Wt), C is g_P (ldc=1024), N_store=1023
    {
        dim3 grid(1024 / BN, BATCH / BM);
        sgemm_kernel<true><<<grid, 256>>>(X, Wt, P, BATCH, NUM_INNER, IN_DIM,
                                          1024, 1024);
    }

    cascade_kernel<<<BATCH / 2, 256>>>(P, mu, allpp);

    pen_accum_kernel<<<64, 256>>>(P, allpp);
    pen_final_kernel<<<1, 256>>>(pen);

    // GEMM2: logits = mu @ Wlt, N_store=1000, ldc=1000
    {
        dim3 grid(1024 / BN, BATCH / BM);
        sgemm_kernel<false><<<grid, 256>>>(mu, Wlt, logits, BATCH, OUT_DIM,
                                           NUM_LEAF, 1024, 1000);
    }
}

// round 3
// speedup vs baseline: 2.7491x; 2.7491x over previous
#include <cuda_runtime.h>
#include <math.h>
#include <cstdint>

// ---------------------------------------------------------------------------
// Problem constants
// ---------------------------------------------------------------------------
#define BATCH      8192
#define IN_DIM     2048
#define OUT_DIM    1000
#define DEPTH      10
#define NUM_INNER  1023
#define NUM_LEAF   1024
#define ALLPP_COLS 2047

#define LOGITS_OFF 0
#define MU_OFF     (BATCH * OUT_DIM)
#define PEN_OFF    (MU_OFF + BATCH * NUM_LEAF)
#define ALLPP_OFF  (PEN_OFF + 1)

// ---------------------------------------------------------------------------
// Scratch
// ---------------------------------------------------------------------------
__device__ __align__(128) float g_P[BATCH * 1024];     // sigmoid outputs (32 MB)
__device__ __align__(128) float g_Bi[1024 * 2048];     // W_inner[:,1:], [n][k] (8 MB)
__device__ __align__(128) float g_bias[1024];
__device__ float g_num[1024];
__device__ float g_den[1024];

// ---------------------------------------------------------------------------
// Helpers
// ---------------------------------------------------------------------------
__device__ __forceinline__ uint32_t smem_u32(const void* p) {
    uint32_t a;
    asm("{ .reg .u64 t; cvta.to.shared.u64 t, %1; cvt.u32.u64 %0, t; }"
        : "=r"(a) : "l"(p));
    return a;
}
__device__ __forceinline__ void cp16(uint32_t dst, const void* src, uint32_t nbytes) {
    asm volatile("cp.async.cg.shared.global [%0], [%1], 16, %2;"
                 :: "r"(dst), "l"(src), "r"(nbytes));
}
__device__ __forceinline__ uint32_t f2tf32(float v) {
    uint32_t r;
    asm("cvt.rna.tf32.f32 %0, %1;" : "=r"(r) : "f"(v));
    return r;
}

// ---------------------------------------------------------------------------
// tf32 mma.sync GEMM: C[M, nstore] = A[M,K] * B[:,K]^T (B rows = output cols)
// BM=BN=128, BK=32, 3 stages, 8 warps (2 M x 4 N), warp tile 64x32.
// ---------------------------------------------------------------------------
#define BM 128
#define BN 128
#define BK 32
#define STAGES 3
#define LDS_ROW 36                         // BK + 4 pad (floats)
#define TILE_F (128 * LDS_ROW)             // floats per tile (A or B)
#define GEMM_SMEM (STAGES * 2 * TILE_F * 4)

template <bool SIG, bool BPRED>
__global__ __launch_bounds__(256, 1)
void mgemm(const float* __restrict__ A, int lda,
           const float* __restrict__ B, int ldb, int bvalid,
           float* __restrict__ C, int ldc, int nstore, int K)
{
    extern __shared__ float sm[];
    float* Asm = sm;                         // [STAGES][128][36]
    float* Bsm = sm + STAGES * TILE_F;       // [STAGES][128][36]

    const int tid  = threadIdx.x;
    const int lane = tid & 31;
    const int warp = tid >> 5;
    const int g = lane >> 2;                 // group id (row within 8)
    const int t = lane & 3;                  // thread-in-group
    const int wm = warp & 1;                 // 0..1  -> M offset 64*wm
    const int wn = warp >> 1;                // 0..3  -> N offset 32*wn
    const int bm = blockIdx.y * BM;
    const int bn = blockIdx.x * BN;

    float c[4][4][4];
#pragma unroll
    for (int i = 0; i < 4; i++)
#pragma unroll
        for (int j = 0; j < 4; j++)
#pragma unroll
            for (int e = 0; e < 4; e++) c[i][j][e] = 0.f;

    const int nchunk = K / BK;

    // ---- stage loader ----
    auto load_stage = [&](int ic, int s) {
        float* as = Asm + s * TILE_F;
        float* bs = Bsm + s * TILE_F;
        const int k0 = ic * BK;
#pragma unroll
        for (int it = 0; it < 4; ++it) {
            int seg = tid + it * 256;        // 1024 chunks of 16B
            int row = seg >> 3, u = seg & 7;
            cp16(smem_u32(as + row * LDS_ROW + u * 4),
                 A + (size_t)(bm + row) * lda + k0 + u * 4, 16);
        }
#pragma unroll
        for (int it = 0; it < 4; ++it) {
            int seg = tid + it * 256;
            int row = seg >> 3, u = seg & 7;
            int gn = bn + row;
            uint32_t nb = 16;
            int srow = gn;
            if (BPRED && gn >= bvalid) { nb = 0; srow = 0; }
            cp16(smem_u32(bs + row * LDS_ROW + u * 4),
                 B + (size_t)srow * ldb + k0 + u * 4, nb);
        }
    };

    // prologue
#pragma unroll
    for (int ic = 0; ic < STAGES - 1; ++ic) {
        load_stage(ic, ic);
        asm volatile("cp.async.commit_group;" ::: "memory");
    }

    for (int i = 0; i < nchunk; ++i) {
        asm volatile("cp.async.wait_group 1;" ::: "memory");
        __syncthreads();

        int pf = i + STAGES - 1;
        if (pf < nchunk) load_stage(pf, pf % STAGES);
        asm volatile("cp.async.commit_group;" ::: "memory");

        const int s = i % STAGES;
        const float* as = Asm + s * TILE_F + (wm * 64 + g) * LDS_ROW + t;
        const float* bs = Bsm + s * TILE_F + (wn * 32 + g) * LDS_ROW + t;

#pragma unroll
        for (int kk = 0; kk < 4; ++kk) {
            uint32_t a[4][4], b[4][2];
#pragma unroll
            for (int mt = 0; mt < 4; ++mt) {
                const float* p = as + mt * (16 * LDS_ROW) + kk * 8;
                a[mt][0] = f2tf32(p[0]);
                a[mt][1] = f2tf32(p[8 * LDS_ROW]);
                a[mt][2] = f2tf32(p[4]);
                a[mt][3] = f2tf32(p[8 * LDS_ROW + 4]);
            }
#pragma unroll
            for (int nt = 0; nt < 4; ++nt) {
                const float* p = bs + nt * (8 * LDS_ROW) + kk * 8;
                b[nt][0] = f2tf32(p[0]);
                b[nt][1] = f2tf32(p[4]);
            }
#pragma unroll
            for (int mt = 0; mt < 4; ++mt)
#pragma unroll
                for (int nt = 0; nt < 4; ++nt) {
                    asm volatile(
                        "mma.sync.aligned.m16n8k8.row.col.f32.tf32.tf32.f32 "
                        "{%0,%1,%2,%3}, {%4,%5,%6,%7}, {%8,%9}, {%0,%1,%2,%3};"
                        : "+f"(c[mt][nt][0]), "+f"(c[mt][nt][1]),
                          "+f"(c[mt][nt][2]), "+f"(c[mt][nt][3])
                        : "r"(a[mt][0]), "r"(a[mt][1]), "r"(a[mt][2]), "r"(a[mt][3]),
                          "r"(b[nt][0]), "r"(b[nt][1]));
                }
        }
    }

    // ---- epilogue ----
#pragma unroll
    for (int mt = 0; mt < 4; ++mt) {
        const int r0 = bm + wm * 64 + mt * 16 + g;
#pragma unroll
        for (int nt = 0; nt < 4; ++nt) {
            const int col = bn + wn * 32 + nt * 8 + t * 2;
            if (col + 1 < nstore || col < nstore) {
                float v0 = c[mt][nt][0], v1 = c[mt][nt][1];
                float v2 = c[mt][nt][2], v3 = c[mt][nt][3];
                if (SIG) {
                    const float b0 = g_bias[col], b1 = g_bias[col + 1];
                    v0 = 1.f / (1.f + __expf(-(v0 + b0)));
                    v1 = 1.f / (1.f + __expf(-(v1 + b1)));
                    v2 = 1.f / (1.f + __expf(-(v2 + b0)));
                    v3 = 1.f / (1.f + __expf(-(v3 + b1)));
                }
                if (col + 1 < nstore) {
                    *(float2*)&C[(size_t)r0 * ldc + col]       = make_float2(v0, v1);
                    *(float2*)&C[(size_t)(r0 + 8) * ldc + col] = make_float2(v2, v3);
                } else {
                    C[(size_t)r0 * ldc + col]       = v0;
                    C[(size_t)(r0 + 8) * ldc + col] = v2;
                }
            }
        }
    }
}

// ---------------------------------------------------------------------------
// Prep / cascade / penalty
// ---------------------------------------------------------------------------
__global__ void zero_acc_kernel() {
    int tn = threadIdx.x;
    g_num[tn] = 0.f;
    g_den[tn] = 0.f;
}

// g_Bi[n][k] = W_inner[n][k+1] (n<1023 else 0); bias[n] = W_inner[n][0]
__global__ void prep_winner_kernel(const float* __restrict__ Wi) {
    int idx = blockIdx.x * blockDim.x + threadIdx.x;   // over 1024*2048
    if (idx >= 1024 * 2048) return;
    int n = idx >> 11;
    int k = idx & 2047;
    float v = 0.f;
    if (n < NUM_INNER) v = Wi[(size_t)n * (IN_DIM + 1) + 1 + k];
    g_Bi[(size_t)n * 2048 + k] = v;
    if (k == 0) g_bias[n] = (n < NUM_INNER) ? Wi[(size_t)n * (IN_DIM + 1)] : 0.f;
}

__global__ __launch_bounds__(256)
void cascade_kernel(const float* __restrict__ P, float* __restrict__ mu_out,
                    float* __restrict__ allpp)
{
    const int ROWS = 2;
    __shared__ float p_sh[ROWS][1024];
    __shared__ float buf[2][ROWS][1024];

    const int tid = threadIdx.x;
    const int b0 = blockIdx.x * ROWS;

#pragma unroll
    for (int r = 0; r < ROWS; r++)
        for (int j = tid; j < NUM_INNER; j += 256)
            p_sh[r][j] = P[(size_t)(b0 + r) * 1024 + j];

    if (tid < ROWS) {
        buf[0][tid][0] = 1.f;
        allpp[(size_t)(b0 + tid) * ALLPP_COLS + 0] = 1.f;
    }
    __syncthreads();

    int cur = 0;
    for (int lvl = 0; lvl < DEPTH; lvl++) {
        const int n = 1 << lvl;
        const int start = n - 1;
        const int outbase = 2 * n - 1;
        const int total = ROWS * 2 * n;
        for (int idx = tid; idx < total; idx += 256) {
            int r  = idx / (2 * n);
            int jj = idx - r * (2 * n);
            int j  = jj >> 1;
            int cc = jj & 1;
            float pm = p_sh[r][start + j];
            float v  = buf[cur][r][j] * (cc ? pm : (1.f - pm));
            buf[cur ^ 1][r][jj] = v;
            allpp[(size_t)(b0 + r) * ALLPP_COLS + outbase + jj] = v;
            if (lvl == DEPTH - 1)
                mu_out[(size_t)(b0 + r) * NUM_LEAF + jj] = v;
        }
        __syncthreads();
        cur ^= 1;
    }
}

__global__ __launch_bounds__(256)
void pen_accum_kernel(const float* __restrict__ P, const float* __restrict__ allpp)
{
    __shared__ float s_num[NUM_INNER];
    __shared__ float s_den[NUM_INNER];
    const int tid = threadIdx.x;
    for (int k = tid; k < NUM_INNER; k += 256) { s_num[k] = 0.f; s_den[k] = 0.f; }
    __syncthreads();

    const int rows_per_block = BATCH / gridDim.x;
    const int b0 = blockIdx.x * rows_per_block;
    for (int b = b0; b < b0 + rows_per_block; b++) {
        const float* mu_row = allpp + (size_t)b * ALLPP_COLS;
        const float* p_row  = P + (size_t)b * 1024;
        for (int k = tid; k < NUM_INNER; k += 256) {
            float m = mu_row[k];
            s_num[k] += p_row[k] * m;
            s_den[k] += m;
        }
    }
    __syncthreads();
    for (int k = tid; k < NUM_INNER; k += 256) {
        atomicAdd(&g_num[k], s_num[k]);
        atomicAdd(&g_den[k], s_den[k]);
    }
}

__global__ __launch_bounds__(256)
void pen_final_kernel(float* __restrict__ pen_out)
{
    __shared__ float red[256];
    const int tid = threadIdx.x;
    float local = 0.f;
    for (int k = tid; k < NUM_INNER; k += 256) {
        float alpha = g_num[k] / g_den[k];
        float pen = logf(alpha) + logf(1.f - alpha);
        if (!isfinite(pen)) pen = 0.f;
        int lvl = 31 - __clz(k + 1);
        float w = ldexpf(0.5f, -lvl);
        local -= w * pen;
    }
    red[tid] = local;
    __syncthreads();
    for (int s = 128; s > 0; s >>= 1) {
        if (tid < s) red[tid] += red[tid + s];
        __syncthreads();
    }
    if (tid == 0) pen_out[0] = red[0];
}

// ---------------------------------------------------------------------------
// Launch
// ---------------------------------------------------------------------------
extern "C" void kernel_launch(void* const* d_in, const int* in_sizes, int n_in,
                              void* d_out, int out_size)
{
    const float* X  = (const float*)d_in[0];
    const float* Wi = (const float*)d_in[1];
    const float* Wl = (const float*)d_in[2];
    float* out = (float*)d_out;

    float* logits = out + LOGITS_OFF;
    float* mu     = out + MU_OFF;
    float* pen    = out + PEN_OFF;
    float* allpp  = out + ALLPP_OFF;

    float* P  = nullptr;
    float* Bi = nullptr;
    cudaGetSymbolAddress((void**)&P,  g_P);
    cudaGetSymbolAddress((void**)&Bi, g_Bi);

    cudaFuncSetAttribute(mgemm<true, false>,
                         cudaFuncAttributeMaxDynamicSharedMemorySize, GEMM_SMEM);
    cudaFuncSetAttribute(mgemm<false, true>,
                         cudaFuncAttributeMaxDynamicSharedMemorySize, GEMM_SMEM);

    zero_acc_kernel<<<1, 1024>>>();
    prep_winner_kernel<<<(1024 * 2048 + 255) / 256, 256>>>(Wi);

    // GEMM1: P = sigmoid(bias + X @ g_Bi^T)   [8192 x 1024], K=2048
    {
        dim3 grid(1024 / BN, BATCH / BM);
        mgemm<true, false><<<grid, 256, GEMM_SMEM>>>(
            X, IN_DIM, Bi, IN_DIM, 1024, P, 1024, 1024, IN_DIM);
    }

    cascade_kernel<<<BATCH / 2, 256>>>(P, mu, allpp);

    pen_accum_kernel<<<256, 256>>>(P, allpp);
    pen_final_kernel<<<1, 256>>>(pen);

    // GEMM2: logits = mu @ W_leaf^T   [8192 x 1000], K=1024 (B rows >=1000 zero)
    {
        dim3 grid(1024 / BN, BATCH / BM);
        mgemm<false, true><<<grid, 256, GEMM_SMEM>>>(
            mu, NUM_LEAF, Wl, NUM_LEAF, OUT_DIM, logits, OUT_DIM, OUT_DIM, NUM_LEAF);
    }
}

// round 4
// speedup vs baseline: 3.1580x; 1.1487x over previous
#include <cuda_runtime.h>
#include <math.h>
#include <cstdint>

// ---------------------------------------------------------------------------
// Problem constants
// ---------------------------------------------------------------------------
#define BATCH      8192
#define IN_DIM     2048
#define OUT_DIM    1000
#define DEPTH      10
#define NUM_INNER  1023
#define NUM_LEAF   1024
#define ALLPP_COLS 2047

#define LOGITS_OFF 0
#define MU_OFF     (BATCH * OUT_DIM)
#define PEN_OFF    (MU_OFF + BATCH * NUM_LEAF)
#define ALLPP_OFF  (PEN_OFF + 1)

// ---------------------------------------------------------------------------
// Scratch
// ---------------------------------------------------------------------------
__device__ __align__(128) float g_Xr[BATCH * IN_DIM];  // tf32-rounded X; later rounded mu (64 MB)
__device__ __align__(128) float g_P[BATCH * 1024];     // sigmoid outputs (32 MB)
__device__ __align__(128) float g_Bi[1024 * 2048];     // rounded W_inner[:,1:] (8 MB)
__device__ __align__(128) float g_Bl[1024 * 1024];     // rounded, padded W_leaf (4 MB)
__device__ __align__(128) float g_bias[1024];
__device__ float g_num[1024];
__device__ float g_den[1024];

// ---------------------------------------------------------------------------
// Helpers
// ---------------------------------------------------------------------------
__device__ __forceinline__ uint32_t smem_u32(const void* p) {
    uint32_t a;
    asm("{ .reg .u64 t; cvta.to.shared.u64 t, %1; cvt.u32.u64 %0, t; }"
        : "=r"(a) : "l"(p));
    return a;
}
__device__ __forceinline__ void cp16(uint32_t dst, const void* src) {
    asm volatile("cp.async.cg.shared.global [%0], [%1], 16;"
                 :: "r"(dst), "l"(src));
}
__device__ __forceinline__ float rtf32(float v) {
    uint32_t r;
    asm("cvt.rna.tf32.f32 %0, %1;" : "=r"(r) : "f"(v));
    return __uint_as_float(r);
}

// ---------------------------------------------------------------------------
// tf32 mma.sync GEMM: C[M, nstore] = A[M,K] * B[:,K]^T (B rows = output cols).
// Operands MUST be pre-rounded to tf32. BM=256, BN=128, BK=32, 3 stages,
// 8 warps in 4(M) x 2(N), warp tile 64x64.
// ---------------------------------------------------------------------------
#define BM 256
#define BN 128
#define BK 32
#define STAGES 3
#define LDS_ROW 36                          // BK + 4 pad (floats)
#define A_TILE_F (BM * LDS_ROW)             // 9216
#define B_TILE_F (BN * LDS_ROW)             // 4608
#define GEMM_SMEM (STAGES * (A_TILE_F + B_TILE_F) * 4)   // 165888 B

template <bool SIG>
__global__ __launch_bounds__(256, 1)
void mgemm(const float* __restrict__ A, int lda,
           const float* __restrict__ B, int ldb,
           float* __restrict__ C, int ldc, int nstore, int K)
{
    extern __shared__ float sm[];
    float* Asm = sm;                          // [STAGES][256][36]
    float* Bsm = sm + STAGES * A_TILE_F;      // [STAGES][128][36]

    const int tid  = threadIdx.x;
    const int lane = tid & 31;
    const int warp = tid >> 5;
    const int g  = lane >> 2;                 // 0..7
    const int t  = lane & 3;                  // 0..3
    const int wm = warp & 3;                  // M offset 64*wm
    const int wn = warp >> 2;                 // N offset 64*wn
    const int bm = blockIdx.y * BM;
    const int bn = blockIdx.x * BN;

    float c[4][8][4];
#pragma unroll
    for (int i = 0; i < 4; i++)
#pragma unroll
        for (int j = 0; j < 8; j++)
#pragma unroll
            for (int e = 0; e < 4; e++) c[i][j][e] = 0.f;

    const int nchunk = K / BK;

    auto load_stage = [&](int ic, int s) {
        float* as = Asm + s * A_TILE_F;
        float* bs = Bsm + s * B_TILE_F;
        const int k0 = ic * BK;
#pragma unroll
        for (int it = 0; it < 8; ++it) {       // A: 256 rows x 8 x 16B
            int seg = tid + it * 256;
            int row = seg >> 3, u = seg & 7;
            cp16(smem_u32(as + row * LDS_ROW + u * 4),
                 A + (size_t)(bm + row) * lda + k0 + u * 4);
        }
#pragma unroll
        for (int it = 0; it < 4; ++it) {       // B: 128 rows x 8 x 16B
            int seg = tid + it * 256;
            int row = seg >> 3, u = seg & 7;
            cp16(smem_u32(bs + row * LDS_ROW + u * 4),
                 B + (size_t)(bn + row) * ldb + k0 + u * 4);
        }
    };

#pragma unroll
    for (int ic = 0; ic < STAGES - 1; ++ic) {
        load_stage(ic, ic);
        asm volatile("cp.async.commit_group;" ::: "memory");
    }

    for (int i = 0; i < nchunk; ++i) {
        asm volatile("cp.async.wait_group 1;" ::: "memory");
        __syncthreads();

        int pf = i + STAGES - 1;
        if (pf < nchunk) load_stage(pf, pf % STAGES);
        asm volatile("cp.async.commit_group;" ::: "memory");

        const int s = i % STAGES;
        const uint32_t* as = (const uint32_t*)(Asm + s * A_TILE_F
                               + (wm * 64 + g) * LDS_ROW + t);
        const uint32_t* bs = (const uint32_t*)(Bsm + s * B_TILE_F
                               + (wn * 64 + g) * LDS_ROW + t);

#pragma unroll
        for (int kk = 0; kk < 4; ++kk) {
            uint32_t a[4][4], b[8][2];
#pragma unroll
            for (int mt = 0; mt < 4; ++mt) {
                const uint32_t* p = as + mt * (16 * LDS_ROW) + kk * 8;
                a[mt][0] = p[0];
                a[mt][1] = p[8 * LDS_ROW];
                a[mt][2] = p[4];
                a[mt][3] = p[8 * LDS_ROW + 4];
            }
#pragma unroll
            for (int nt = 0; nt < 8; ++nt) {
                const uint32_t* q = bs + nt * (8 * LDS_ROW) + kk * 8;
                b[nt][0] = q[0];
                b[nt][1] = q[4];
            }
#pragma unroll
            for (int mt = 0; mt < 4; ++mt)
#pragma unroll
                for (int nt = 0; nt < 8; ++nt) {
                    asm volatile(
                        "mma.sync.aligned.m16n8k8.row.col.f32.tf32.tf32.f32 "
                        "{%0,%1,%2,%3}, {%4,%5,%6,%7}, {%8,%9}, {%0,%1,%2,%3};"
                        : "+f"(c[mt][nt][0]), "+f"(c[mt][nt][1]),
                          "+f"(c[mt][nt][2]), "+f"(c[mt][nt][3])
                        : "r"(a[mt][0]), "r"(a[mt][1]), "r"(a[mt][2]), "r"(a[mt][3]),
                          "r"(b[nt][0]), "r"(b[nt][1]));
                }
        }
    }

    // ---- epilogue ----
#pragma unroll
    for (int mt = 0; mt < 4; ++mt) {
        const int r0 = bm + wm * 64 + mt * 16 + g;
#pragma unroll
        for (int nt = 0; nt < 8; ++nt) {
            const int col = bn + wn * 64 + nt * 8 + t * 2;
            if (col < nstore) {
                float v0 = c[mt][nt][0], v1 = c[mt][nt][1];
                float v2 = c[mt][nt][2], v3 = c[mt][nt][3];
                if (SIG) {
                    const float b0 = g_bias[col], b1 = g_bias[col + 1];
                    v0 = 1.f / (1.f + __expf(-(v0 + b0)));
                    v1 = 1.f / (1.f + __expf(-(v1 + b1)));
                    v2 = 1.f / (1.f + __expf(-(v2 + b0)));
                    v3 = 1.f / (1.f + __expf(-(v3 + b1)));
                }
                if (col + 1 < nstore) {
                    *(float2*)&C[(size_t)r0 * ldc + col]       = make_float2(v0, v1);
                    *(float2*)&C[(size_t)(r0 + 8) * ldc + col] = make_float2(v2, v3);
                } else {
                    C[(size_t)r0 * ldc + col]       = v0;
                    C[(size_t)(r0 + 8) * ldc + col] = v2;
                }
            }
        }
    }
}

// ---------------------------------------------------------------------------
// Prep kernels
// ---------------------------------------------------------------------------
__global__ void zero_acc_kernel() {
    int tn = threadIdx.x;
    g_num[tn] = 0.f;
    g_den[tn] = 0.f;
}

__global__ void prep_x_kernel(const float* __restrict__ X) {
    int idx = blockIdx.x * blockDim.x + threadIdx.x;   // over 8192*2048/4
    if (idx >= BATCH * IN_DIM / 4) return;
    float4 v = ((const float4*)X)[idx];
    v.x = rtf32(v.x); v.y = rtf32(v.y); v.z = rtf32(v.z); v.w = rtf32(v.w);
    ((float4*)g_Xr)[idx] = v;
}

// g_Bi[n][k] = round(W_inner[n][k+1]) (n<1023 else 0); bias[n] = W_inner[n][0]
__global__ void prep_winner_kernel(const float* __restrict__ Wi) {
    int idx = blockIdx.x * blockDim.x + threadIdx.x;   // over 1024*2048
    if (idx >= 1024 * 2048) return;
    int n = idx >> 11;
    int k = idx & 2047;
    float v = 0.f;
    if (n < NUM_INNER) v = rtf32(Wi[(size_t)n * (IN_DIM + 1) + 1 + k]);
    g_Bi[(size_t)n * 2048 + k] = v;
    if (k == 0) g_bias[n] = (n < NUM_INNER) ? Wi[(size_t)n * (IN_DIM + 1)] : 0.f;
}

// g_Bl[n][k] = round(W_leaf[n][k]) (n<1000 else 0)
__global__ void prep_wleaf_kernel(const float* __restrict__ Wl) {
    int idx = blockIdx.x * blockDim.x + threadIdx.x;   // over 1024*1024
    if (idx >= 1024 * 1024) return;
    int n = idx >> 10;
    int k = idx & 1023;
    g_Bl[idx] = (n < OUT_DIM) ? rtf32(Wl[(size_t)n * NUM_LEAF + k]) : 0.f;
}

// ---------------------------------------------------------------------------
// Cascade: writes exact mu (output), exact all_pp (output) and rounded mu
// into g_Xr (stride 1024) for GEMM2.
// ---------------------------------------------------------------------------
__global__ __launch_bounds__(256)
void cascade_kernel(const float* __restrict__ P, float* __restrict__ mu_out,
                    float* __restrict__ allpp)
{
    const int ROWS = 2;
    __shared__ float p_sh[ROWS][1024];
    __shared__ float buf[2][ROWS][1024];

    const int tid = threadIdx.x;
    const int b0 = blockIdx.x * ROWS;

#pragma unroll
    for (int r = 0; r < ROWS; r++)
        for (int j = tid; j < NUM_INNER; j += 256)
            p_sh[r][j] = P[(size_t)(b0 + r) * 1024 + j];

    if (tid < ROWS) {
        buf[0][tid][0] = 1.f;
        allpp[(size_t)(b0 + tid) * ALLPP_COLS + 0] = 1.f;
    }
    __syncthreads();

    int cur = 0;
    for (int lvl = 0; lvl < DEPTH; lvl++) {
        const int n = 1 << lvl;
        const int start = n - 1;
        const int outbase = 2 * n - 1;
        const int total = ROWS * 2 * n;
        for (int idx = tid; idx < total; idx += 256) {
            int r  = idx / (2 * n);
            int jj = idx - r * (2 * n);
            int j  = jj >> 1;
            int cc = jj & 1;
            float pm = p_sh[r][start + j];
            float v  = buf[cur][r][j] * (cc ? pm : (1.f - pm));
            buf[cur ^ 1][r][jj] = v;
            allpp[(size_t)(b0 + r) * ALLPP_COLS + outbase + jj] = v;
            if (lvl == DEPTH - 1) {
                mu_out[(size_t)(b0 + r) * NUM_LEAF + jj] = v;
                g_Xr[(size_t)(b0 + r) * 1024 + jj] = rtf32(v);
            }
        }
        __syncthreads();
        cur ^= 1;
    }
}

// ---------------------------------------------------------------------------
// Penalty
// ---------------------------------------------------------------------------
__global__ __launch_bounds__(256)
void pen_accum_kernel(const float* __restrict__ P, const float* __restrict__ allpp)
{
    __shared__ float s_num[NUM_INNER];
    __shared__ float s_den[NUM_INNER];
    const int tid = threadIdx.x;
    for (int k = tid; k < NUM_INNER; k += 256) { s_num[k] = 0.f; s_den[k] = 0.f; }
    __syncthreads();

    const int rows_per_block = BATCH / gridDim.x;
    const int b0 = blockIdx.x * rows_per_block;
    for (int b = b0; b < b0 + rows_per_block; b++) {
        const float* mu_row = allpp + (size_t)b * ALLPP_COLS;
        const float* p_row  = P + (size_t)b * 1024;
        for (int k = tid; k < NUM_INNER; k += 256) {
            float m = mu_row[k];
            s_num[k] += p_row[k] * m;
            s_den[k] += m;
        }
    }
    __syncthreads();
    for (int k = tid; k < NUM_INNER; k += 256) {
        atomicAdd(&g_num[k], s_num[k]);
        atomicAdd(&g_den[k], s_den[k]);
    }
}

__global__ __launch_bounds__(256)
void pen_final_kernel(float* __restrict__ pen_out)
{
    __shared__ float red[256];
    const int tid = threadIdx.x;
    float local = 0.f;
    for (int k = tid; k < NUM_INNER; k += 256) {
        float alpha = g_num[k] / g_den[k];
        float pen = logf(alpha) + logf(1.f - alpha);
        if (!isfinite(pen)) pen = 0.f;
        int lvl = 31 - __clz(k + 1);
        float w = ldexpf(0.5f, -lvl);
        local -= w * pen;
    }
    red[tid] = local;
    __syncthreads();
    for (int s = 128; s > 0; s >>= 1) {
        if (tid < s) red[tid] += red[tid + s];
        __syncthreads();
    }
    if (tid == 0) pen_out[0] = red[0];
}

// ---------------------------------------------------------------------------
// Launch
// ---------------------------------------------------------------------------
extern "C" void kernel_launch(void* const* d_in, const int* in_sizes, int n_in,
                              void* d_out, int out_size)
{
    const float* X  = (const float*)d_in[0];
    const float* Wi = (const float*)d_in[1];
    const float* Wl = (const float*)d_in[2];
    float* out = (float*)d_out;

    float* logits = out + LOGITS_OFF;
    float* mu     = out + MU_OFF;
    float* pen    = out + PEN_OFF;
    float* allpp  = out + ALLPP_OFF;

    float* Xr = nullptr;
    float* P  = nullptr;
    float* Bi = nullptr;
    float* Bl = nullptr;
    cudaGetSymbolAddress((void**)&Xr, g_Xr);
    cudaGetSymbolAddress((void**)&P,  g_P);
    cudaGetSymbolAddress((void**)&Bi, g_Bi);
    cudaGetSymbolAddress((void**)&Bl, g_Bl);

    cudaFuncSetAttribute(mgemm<true>,
                         cudaFuncAttributeMaxDynamicSharedMemorySize, GEMM_SMEM);
    cudaFuncSetAttribute(mgemm<false>,
                         cudaFuncAttributeMaxDynamicSharedMemorySize, GEMM_SMEM);

    zero_acc_kernel<<<1, 1024>>>();
    prep_x_kernel<<<(BATCH * IN_DIM / 4 + 255) / 256, 256>>>(X);
    prep_winner_kernel<<<(1024 * 2048 + 255) / 256, 256>>>(Wi);
    prep_wleaf_kernel<<<(1024 * 1024 + 255) / 256, 256>>>(Wl);

    // GEMM1: P = sigmoid(bias + Xr @ g_Bi^T)   [8192 x 1024], K=2048
    {
        dim3 grid(1024 / BN, BATCH / BM);
        mgemm<true><<<grid, 256, GEMM_SMEM>>>(
            Xr, IN_DIM, Bi, IN_DIM, P, 1024, 1024, IN_DIM);
    }

    cascade_kernel<<<BATCH / 2, 256>>>(P, mu, allpp);

    pen_accum_kernel<<<256, 256>>>(P, allpp);
    pen_final_kernel<<<1, 256>>>(pen);

    // GEMM2: logits = mu_r @ g_Bl^T   [8192 x 1000], K=1024
    {
        dim3 grid(1024 / BN, BATCH / BM);
        mgemm<false><<<grid, 256, GEMM_SMEM>>>(
            Xr, NUM_LEAF, Bl, NUM_LEAF, logits, OUT_DIM, OUT_DIM, NUM_LEAF);
    }
}

// round 5
// speedup vs baseline: 4.3754x; 1.3855x over previous
#include <cuda_runtime.h>
#include <cuda_fp16.h>
#include <math.h>
#include <cstdint>

// ---------------------------------------------------------------------------
// Problem constants
// ---------------------------------------------------------------------------
#define BATCH      8192
#define IN_DIM     2048
#define OUT_DIM    1000
#define DEPTH      10
#define NUM_INNER  1023
#define NUM_LEAF   1024
#define ALLPP_COLS 2047

#define LOGITS_OFF 0
#define MU_OFF     (BATCH * OUT_DIM)
#define PEN_OFF    (MU_OFF + BATCH * NUM_LEAF)
#define ALLPP_OFF  (PEN_OFF + 1)

// ---------------------------------------------------------------------------
// Scratch
// ---------------------------------------------------------------------------
__device__ __align__(128) __half g_Xh[BATCH * IN_DIM];   // fp16 X; later fp16 mu (32 MB)
__device__ __align__(128) float  g_P[BATCH * 1024];      // sigmoid outputs (32 MB)
__device__ __align__(128) __half g_Bih[1024 * 2048];     // fp16 W_inner[:,1:] (4 MB)
__device__ __align__(128) __half g_Blh[1024 * 1024];     // fp16 padded W_leaf (2 MB)
__device__ __align__(128) float  g_bias[1024];
__device__ float g_num[1024];
__device__ float g_den[1024];

// ---------------------------------------------------------------------------
// Helpers
// ---------------------------------------------------------------------------
__device__ __forceinline__ uint32_t smem_u32(const void* p) {
    uint32_t a;
    asm("{ .reg .u64 t; cvta.to.shared.u64 t, %1; cvt.u32.u64 %0, t; }"
        : "=r"(a) : "l"(p));
    return a;
}
__device__ __forceinline__ void cp16(uint32_t dst, const void* src) {
    asm volatile("cp.async.cg.shared.global [%0], [%1], 16;"
                 :: "r"(dst), "l"(src));
}

// ---------------------------------------------------------------------------
// fp16 mma.sync GEMM: C[M, nstore] = A[M,K] * B[:,K]^T (fp32 accum).
// A, B are fp16 (pre-converted). BM=256, BN=128, BK=32, 3 stages,
// 8 warps in 4(M) x 2(N), warp tile 64x64, m16n8k16.
// ---------------------------------------------------------------------------
#define BM 256
#define BN 128
#define BK 32
#define STAGES 3
#define ROW_H 40                             // BK halves + 8 pad
#define ROW_U 20                             // in u32
#define A_TILE_H (BM * ROW_H)                // 10240 halves
#define B_TILE_H (BN * ROW_H)                // 5120 halves
#define GEMM_SMEM (STAGES * (A_TILE_H + B_TILE_H) * 2)   // 92160 B

template <bool SIG>
__global__ __launch_bounds__(256, 1)
void mgemm(const __half* __restrict__ A, int lda,
           const __half* __restrict__ B, int ldb,
           float* __restrict__ C, int ldc, int nstore, int K)
{
    extern __shared__ __half smh[];
    __half* Asm = smh;
    __half* Bsm = smh + STAGES * A_TILE_H;

    const int tid  = threadIdx.x;
    const int lane = tid & 31;
    const int warp = tid >> 5;
    const int g  = lane >> 2;
    const int t  = lane & 3;
    const int wm = warp & 3;                  // M offset 64*wm
    const int wn = warp >> 2;                 // N offset 64*wn
    const int bm = blockIdx.y * BM;
    const int bn = blockIdx.x * BN;

    float c[4][8][4];
#pragma unroll
    for (int i = 0; i < 4; i++)
#pragma unroll
        for (int j = 0; j < 8; j++)
#pragma unroll
            for (int e = 0; e < 4; e++) c[i][j][e] = 0.f;

    const int nchunk = K / BK;

    auto load_stage = [&](int ic, int s) {
        __half* as = Asm + s * A_TILE_H;
        __half* bs = Bsm + s * B_TILE_H;
        const int k0 = ic * BK;
#pragma unroll
        for (int it = 0; it < 4; ++it) {       // A: 256 rows x 4 x 16B(8h)
            int seg = tid + it * 256;
            int row = seg >> 2, u = seg & 3;
            cp16(smem_u32(as + row * ROW_H + u * 8),
                 A + (size_t)(bm + row) * lda + k0 + u * 8);
        }
#pragma unroll
        for (int it = 0; it < 2; ++it) {       // B: 128 rows x 4 x 16B
            int seg = tid + it * 256;
            int row = seg >> 2, u = seg & 3;
            cp16(smem_u32(bs + row * ROW_H + u * 8),
                 B + (size_t)(bn + row) * ldb + k0 + u * 8);
        }
    };

#pragma unroll
    for (int ic = 0; ic < STAGES - 1; ++ic) {
        load_stage(ic, ic);
        asm volatile("cp.async.commit_group;" ::: "memory");
    }

    for (int i = 0; i < nchunk; ++i) {
        asm volatile("cp.async.wait_group 1;" ::: "memory");
        __syncthreads();

        int pf = i + STAGES - 1;
        if (pf < nchunk) load_stage(pf, pf % STAGES);
        asm volatile("cp.async.commit_group;" ::: "memory");

        const int s = i % STAGES;
        const uint32_t* asu = (const uint32_t*)(Asm + s * A_TILE_H)
                              + (wm * 64 + g) * ROW_U + t;
        const uint32_t* bsu = (const uint32_t*)(Bsm + s * B_TILE_H)
                              + (wn * 64 + g) * ROW_U + t;

#pragma unroll
        for (int ks = 0; ks < 2; ++ks) {       // two k16 steps per chunk
            uint32_t a[4][4], b[8][2];
#pragma unroll
            for (int mt = 0; mt < 4; ++mt) {
                const uint32_t* p = asu + mt * (16 * ROW_U) + ks * 8;
                a[mt][0] = p[0];
                a[mt][1] = p[8 * ROW_U];
                a[mt][2] = p[4];
                a[mt][3] = p[8 * ROW_U + 4];
            }
#pragma unroll
            for (int nt = 0; nt < 8; ++nt) {
                const uint32_t* q = bsu + nt * (8 * ROW_U) + ks * 8;
                b[nt][0] = q[0];
                b[nt][1] = q[4];
            }
#pragma unroll
            for (int mt = 0; mt < 4; ++mt)
#pragma unroll
                for (int nt = 0; nt < 8; ++nt) {
                    asm volatile(
                        "mma.sync.aligned.m16n8k16.row.col.f32.f16.f16.f32 "
                        "{%0,%1,%2,%3}, {%4,%5,%6,%7}, {%8,%9}, {%0,%1,%2,%3};"
                        : "+f"(c[mt][nt][0]), "+f"(c[mt][nt][1]),
                          "+f"(c[mt][nt][2]), "+f"(c[mt][nt][3])
                        : "r"(a[mt][0]), "r"(a[mt][1]), "r"(a[mt][2]), "r"(a[mt][3]),
                          "r"(b[nt][0]), "r"(b[nt][1]));
                }
        }
    }

    // ---- epilogue ----
#pragma unroll
    for (int mt = 0; mt < 4; ++mt) {
        const int r0 = bm + wm * 64 + mt * 16 + g;
#pragma unroll
        for (int nt = 0; nt < 8; ++nt) {
            const int col = bn + wn * 64 + nt * 8 + t * 2;
            if (col < nstore) {
                float v0 = c[mt][nt][0], v1 = c[mt][nt][1];
                float v2 = c[mt][nt][2], v3 = c[mt][nt][3];
                if (SIG) {
                    const float b0 = g_bias[col], b1 = g_bias[col + 1];
                    v0 = 1.f / (1.f + __expf(-(v0 + b0)));
                    v1 = 1.f / (1.f + __expf(-(v1 + b1)));
                    v2 = 1.f / (1.f + __expf(-(v2 + b0)));
                    v3 = 1.f / (1.f + __expf(-(v3 + b1)));
                }
                if (col + 1 < nstore) {
                    *(float2*)&C[(size_t)r0 * ldc + col]       = make_float2(v0, v1);
                    *(float2*)&C[(size_t)(r0 + 8) * ldc + col] = make_float2(v2, v3);
                } else {
                    C[(size_t)r0 * ldc + col]       = v0;
                    C[(size_t)(r0 + 8) * ldc + col] = v2;
                }
            }
        }
    }
}

// ---------------------------------------------------------------------------
// Prep kernels
// ---------------------------------------------------------------------------
__global__ void zero_acc_kernel() {
    int tn = threadIdx.x;
    g_num[tn] = 0.f;
    g_den[tn] = 0.f;
}

__global__ void prep_x_kernel(const float* __restrict__ X) {
    int idx = blockIdx.x * blockDim.x + threadIdx.x;   // over 8192*2048/4
    if (idx >= BATCH * IN_DIM / 4) return;
    float4 v = ((const float4*)X)[idx];
    __half2 h0 = __floats2half2_rn(v.x, v.y);
    __half2 h1 = __floats2half2_rn(v.z, v.w);
    ((__half2*)g_Xh)[idx * 2]     = h0;
    ((__half2*)g_Xh)[idx * 2 + 1] = h1;
}

// g_Bih[n][k] = fp16(W_inner[n][k+1]) (n<1023 else 0); bias[n] = W_inner[n][0]
__global__ void prep_winner_kernel(const float* __restrict__ Wi) {
    int idx = blockIdx.x * blockDim.x + threadIdx.x;   // over 1024*2048
    if (idx >= 1024 * 2048) return;
    int n = idx >> 11;
    int k = idx & 2047;
    float v = 0.f;
    if (n < NUM_INNER) v = Wi[(size_t)n * (IN_DIM + 1) + 1 + k];
    g_Bih[idx] = __float2half_rn(v);
    if (k == 0) g_bias[n] = (n < NUM_INNER) ? Wi[(size_t)n * (IN_DIM + 1)] : 0.f;
}

// g_Blh[n][k] = fp16(W_leaf[n][k]) (n<1000 else 0)
__global__ void prep_wleaf_kernel(const float* __restrict__ Wl) {
    int idx = blockIdx.x * blockDim.x + threadIdx.x;   // over 1024*1024
    if (idx >= 1024 * 1024) return;
    int n = idx >> 10;
    int k = idx & 1023;
    float v = (n < OUT_DIM) ? Wl[(size_t)n * NUM_LEAF + k] : 0.f;
    g_Blh[idx] = __float2half_rn(v);
}

// ---------------------------------------------------------------------------
// Cascade: exact mu + all_pp to output; fp16 mu copy into g_Xh for GEMM2.
// ---------------------------------------------------------------------------
__global__ __launch_bounds__(256)
void cascade_kernel(const float* __restrict__ P, float* __restrict__ mu_out,
                    float* __restrict__ allpp)
{
    const int ROWS = 2;
    __shared__ float p_sh[ROWS][1024];
    __shared__ float buf[2][ROWS][1024];

    const int tid = threadIdx.x;
    const int b0 = blockIdx.x * ROWS;

#pragma unroll
    for (int r = 0; r < ROWS; r++)
        for (int j = tid; j < NUM_INNER; j += 256)
            p_sh[r][j] = P[(size_t)(b0 + r) * 1024 + j];

    if (tid < ROWS) {
        buf[0][tid][0] = 1.f;
        allpp[(size_t)(b0 + tid) * ALLPP_COLS + 0] = 1.f;
    }
    __syncthreads();

    int cur = 0;
    for (int lvl = 0; lvl < DEPTH; lvl++) {
        const int n = 1 << lvl;
        const int start = n - 1;
        const int outbase = 2 * n - 1;
        const int total = ROWS * 2 * n;
        for (int idx = tid; idx < total; idx += 256) {
            int r  = idx / (2 * n);
            int jj = idx - r * (2 * n);
            int j  = jj >> 1;
            int cc = jj & 1;
            float pm = p_sh[r][start + j];
            float v  = buf[cur][r][j] * (cc ? pm : (1.f - pm));
            buf[cur ^ 1][r][jj] = v;
            allpp[(size_t)(b0 + r) * ALLPP_COLS + outbase + jj] = v;
            if (lvl == DEPTH - 1) {
                mu_out[(size_t)(b0 + r) * NUM_LEAF + jj] = v;
                g_Xh[(size_t)(b0 + r) * 1024 + jj] = __float2half_rn(v);
            }
        }
        __syncthreads();
        cur ^= 1;
    }
}

// ---------------------------------------------------------------------------
// Penalty
// ---------------------------------------------------------------------------
__global__ __launch_bounds__(256)
void pen_accum_kernel(const float* __restrict__ P, const float* __restrict__ allpp)
{
    __shared__ float s_num[NUM_INNER];
    __shared__ float s_den[NUM_INNER];
    const int tid = threadIdx.x;
    for (int k = tid; k < NUM_INNER; k += 256) { s_num[k] = 0.f; s_den[k] = 0.f; }
    __syncthreads();

    const int rows_per_block = BATCH / gridDim.x;
    const int b0 = blockIdx.x * rows_per_block;
    for (int b = b0; b < b0 + rows_per_block; b++) {
        const float* mu_row = allpp + (size_t)b * ALLPP_COLS;
        const float* p_row  = P + (size_t)b * 1024;
        for (int k = tid; k < NUM_INNER; k += 256) {
            float m = mu_row[k];
            s_num[k] += p_row[k] * m;
            s_den[k] += m;
        }
    }
    __syncthreads();
    for (int k = tid; k < NUM_INNER; k += 256) {
        atomicAdd(&g_num[k], s_num[k]);
        atomicAdd(&g_den[k], s_den[k]);
    }
}

__global__ __launch_bounds__(256)
void pen_final_kernel(float* __restrict__ pen_out)
{
    __shared__ float red[256];
    const int tid = threadIdx.x;
    float local = 0.f;
    for (int k = tid; k < NUM_INNER; k += 256) {
        float alpha = g_num[k] / g_den[k];
        float pen = logf(alpha) + logf(1.f - alpha);
        if (!isfinite(pen)) pen = 0.f;
        int lvl = 31 - __clz(k + 1);
        float w = ldexpf(0.5f, -lvl);
        local -= w * pen;
    }
    red[tid] = local;
    __syncthreads();
    for (int s = 128; s > 0; s >>= 1) {
        if (tid < s) red[tid] += red[tid + s];
        __syncthreads();
    }
    if (tid == 0) pen_out[0] = red[0];
}

// ---------------------------------------------------------------------------
// Launch
// ---------------------------------------------------------------------------
extern "C" void kernel_launch(void* const* d_in, const int* in_sizes, int n_in,
                              void* d_out, int out_size)
{
    const float* X  = (const float*)d_in[0];
    const float* Wi = (const float*)d_in[1];
    const float* Wl = (const float*)d_in[2];
    float* out = (float*)d_out;

    float* logits = out + LOGITS_OFF;
    float* mu     = out + MU_OFF;
    float* pen    = out + PEN_OFF;
    float* allpp  = out + ALLPP_OFF;

    __half* Xh = nullptr;
    float*  P  = nullptr;
    __half* Bi = nullptr;
    __half* Bl = nullptr;
    cudaGetSymbolAddress((void**)&Xh, g_Xh);
    cudaGetSymbolAddress((void**)&P,  g_P);
    cudaGetSymbolAddress((void**)&Bi, g_Bih);
    cudaGetSymbolAddress((void**)&Bl, g_Blh);

    cudaFuncSetAttribute(mgemm<true>,
                         cudaFuncAttributeMaxDynamicSharedMemorySize, GEMM_SMEM);
    cudaFuncSetAttribute(mgemm<false>,
                         cudaFuncAttributeMaxDynamicSharedMemorySize, GEMM_SMEM);

    zero_acc_kernel<<<1, 1024>>>();
    prep_x_kernel<<<(BATCH * IN_DIM / 4 + 255) / 256, 256>>>(X);
    prep_winner_kernel<<<(1024 * 2048 + 255) / 256, 256>>>(Wi);
    prep_wleaf_kernel<<<(1024 * 1024 + 255) / 256, 256>>>(Wl);

    // GEMM1: P = sigmoid(bias + Xh @ g_Bih^T)   [8192 x 1024], K=2048
    {
        dim3 grid(1024 / BN, BATCH / BM);
        mgemm<true><<<grid, 256, GEMM_SMEM>>>(
            Xh, IN_DIM, Bi, IN_DIM, P, 1024, 1024, IN_DIM);
    }

    cascade_kernel<<<BATCH / 2, 256>>>(P, mu, allpp);

    pen_accum_kernel<<<256, 256>>>(P, allpp);
    pen_final_kernel<<<1, 256>>>(pen);

    // GEMM2: logits = mu_h @ g_Blh^T   [8192 x 1000], K=1024
    {
        dim3 grid(1024 / BN, BATCH / BM);
        mgemm<false><<<grid, 256, GEMM_SMEM>>>(
            Xh, NUM_LEAF, Bl, NUM_LEAF, logits, OUT_DIM, OUT_DIM, NUM_LEAF);
    }
}

// round 7
// speedup vs baseline: 4.7068x; 1.0758x over previous
#include <cuda_runtime.h>
#include <cuda_fp16.h>
#include <math.h>
#include <cstdint>

// ---------------------------------------------------------------------------
// Problem constants
// ---------------------------------------------------------------------------
#define BATCH      8192
#define IN_DIM     2048
#define OUT_DIM    1000
#define DEPTH      10
#define NUM_INNER  1023
#define NUM_LEAF   1024
#define ALLPP_COLS 2047

#define LOGITS_OFF 0
#define MU_OFF     (BATCH * OUT_DIM)
#define PEN_OFF    (MU_OFF + BATCH * NUM_LEAF)
#define ALLPP_OFF  (PEN_OFF + 1)

// ---------------------------------------------------------------------------
// Scratch
// ---------------------------------------------------------------------------
__device__ __align__(128) __half g_Xh[BATCH * IN_DIM];   // fp16 X; later fp16 mu (32 MB)
__device__ __align__(128) float  g_P[BATCH * 1024];      // sigmoid outputs (32 MB)
__device__ __align__(128) __half g_Bih[1024 * 2048];     // fp16 W_inner[:,1:] (4 MB)
__device__ __align__(128) __half g_Blh[1024 * 1024];     // fp16 padded W_leaf (2 MB)
__device__ __align__(128) float  g_bias[1024];
__device__ float g_num[1024];
__device__ float g_den[1024];

// ---------------------------------------------------------------------------
// Helpers
// ---------------------------------------------------------------------------
__device__ __forceinline__ uint32_t smem_u32(const void* p) {
    uint32_t a;
    asm("{ .reg .u64 t; cvta.to.shared.u64 t, %1; cvt.u32.u64 %0, t; }"
        : "=r"(a) : "l"(p));
    return a;
}
__device__ __forceinline__ void cp16(uint32_t dst, const void* src) {
    asm volatile("cp.async.cg.shared.global [%0], [%1], 16;"
                 :: "r"(dst), "l"(src));
}
__device__ __forceinline__ void ldsm4(uint32_t& r0, uint32_t& r1,
                                      uint32_t& r2, uint32_t& r3, uint32_t addr) {
    asm volatile("ldmatrix.sync.aligned.m8n8.x4.shared.b16 {%0,%1,%2,%3}, [%4];"
                 : "=r"(r0), "=r"(r1), "=r"(r2), "=r"(r3) : "r"(addr));
}

// ---------------------------------------------------------------------------
// fp16 mma.sync GEMM: C[M, nstore] = A[M,K] * B[:,K]^T (fp32 accum).
// BM=256, BN=128, BK=64, 3 stages, 8 warps 4(M)x2(N), warp tile 64x64.
// Fragments loaded via ldmatrix.x4.
// ---------------------------------------------------------------------------
#define BM 256
#define BN 128
#define BK 64
#define STAGES 3
#define ROW_H 72                             // BK halves + 8 pad (144 B rows)
#define A_TILE_H (BM * ROW_H)                // 18432 halves
#define B_TILE_H (BN * ROW_H)                // 9216 halves
#define GEMM_SMEM (STAGES * (A_TILE_H + B_TILE_H) * 2)   // 165888 B

template <bool SIG>
__global__ __launch_bounds__(256, 1)
void mgemm(const __half* __restrict__ A, int lda,
           const __half* __restrict__ B, int ldb,
           float* __restrict__ C, int ldc, int nstore, int K)
{
    extern __shared__ __half smh[];
    __half* Asm = smh;
    __half* Bsm = smh + STAGES * A_TILE_H;

    const int tid  = threadIdx.x;
    const int lane = tid & 31;
    const int warp = tid >> 5;
    const int g  = lane >> 2;
    const int t  = lane & 3;
    const int wm = warp & 3;                  // M offset 64*wm
    const int wn = warp >> 2;                 // N offset 64*wn
    const int bm = blockIdx.y * BM;
    const int bn = blockIdx.x * BN;

    // ldmatrix lane address components (in halves)
    const int a_lrow = lane & 15;             // row within 16
    const int a_lcol = (lane >> 4) * 8;       // 0 or 8 halves
    const int b_lrow = ((lane >> 4) * 8) + (lane & 7);   // row within 16
    const int b_lcol = ((lane >> 3) & 1) * 8; // 0 or 8 halves

    float c[4][8][4];
#pragma unroll
    for (int i = 0; i < 4; i++)
#pragma unroll
        for (int j = 0; j < 8; j++)
#pragma unroll
            for (int e = 0; e < 4; e++) c[i][j][e] = 0.f;

    const int nchunk = K / BK;

    auto load_stage = [&](int ic, int s) {
        __half* as = Asm + s * A_TILE_H;
        __half* bs = Bsm + s * B_TILE_H;
        const int k0 = ic * BK;
#pragma unroll
        for (int it = 0; it < 8; ++it) {       // A: 256 rows x 8 x 16B(8h)
            int seg = tid + it * 256;
            int row = seg >> 3, u = seg & 7;
            cp16(smem_u32(as + row * ROW_H + u * 8),
                 A + (size_t)(bm + row) * lda + k0 + u * 8);
        }
#pragma unroll
        for (int it = 0; it < 4; ++it) {       // B: 128 rows x 8 x 16B
            int seg = tid + it * 256;
            int row = seg >> 3, u = seg & 7;
            cp16(smem_u32(bs + row * ROW_H + u * 8),
                 B + (size_t)(bn + row) * ldb + k0 + u * 8);
        }
    };

#pragma unroll
    for (int ic = 0; ic < STAGES - 1; ++ic) {
        load_stage(ic, ic);
        asm volatile("cp.async.commit_group;" ::: "memory");
    }

    for (int i = 0; i < nchunk; ++i) {
        asm volatile("cp.async.wait_group 1;" ::: "memory");
        __syncthreads();

        int pf = i + STAGES - 1;
        if (pf < nchunk) load_stage(pf, pf % STAGES);
        asm volatile("cp.async.commit_group;" ::: "memory");

        const int s = i % STAGES;
        const __half* as = Asm + s * A_TILE_H + (wm * 64) * ROW_H;
        const __half* bs = Bsm + s * B_TILE_H + (wn * 64) * ROW_H;
        const uint32_t abase = smem_u32(as + a_lrow * ROW_H + a_lcol);
        const uint32_t bbase = smem_u32(bs + b_lrow * ROW_H + b_lcol);

#pragma unroll
        for (int ks = 0; ks < 4; ++ks) {       // four k16 steps per chunk
            uint32_t a[4][4], b[8][2];
#pragma unroll
            for (int mt = 0; mt < 4; ++mt)
                ldsm4(a[mt][0], a[mt][1], a[mt][2], a[mt][3],
                      abase + (mt * 16 * ROW_H + ks * 16) * 2);
#pragma unroll
            for (int np = 0; np < 4; ++np)     // pairs of n8 tiles
                ldsm4(b[2 * np][0], b[2 * np][1], b[2 * np + 1][0], b[2 * np + 1][1],
                      bbase + (np * 16 * ROW_H + ks * 16) * 2);
#pragma unroll
            for (int mt = 0; mt < 4; ++mt)
#pragma unroll
                for (int nt = 0; nt < 8; ++nt) {
                    asm volatile(
                        "mma.sync.aligned.m16n8k16.row.col.f32.f16.f16.f32 "
                        "{%0,%1,%2,%3}, {%4,%5,%6,%7}, {%8,%9}, {%0,%1,%2,%3};"
                        : "+f"(c[mt][nt][0]), "+f"(c[mt][nt][1]),
                          "+f"(c[mt][nt][2]), "+f"(c[mt][nt][3])
                        : "r"(a[mt][0]), "r"(a[mt][1]), "r"(a[mt][2]), "r"(a[mt][3]),
                          "r"(b[nt][0]), "r"(b[nt][1]));
                }
        }
    }

    // ---- epilogue ----
#pragma unroll
    for (int mt = 0; mt < 4; ++mt) {
        const int r0 = bm + wm * 64 + mt * 16 + g;
#pragma unroll
        for (int nt = 0; nt < 8; ++nt) {
            const int col = bn + wn * 64 + nt * 8 + t * 2;
            if (col < nstore) {
                float v0 = c[mt][nt][0], v1 = c[mt][nt][1];
                float v2 = c[mt][nt][2], v3 = c[mt][nt][3];
                if (SIG) {
                    const float b0 = g_bias[col], b1 = g_bias[col + 1];
                    v0 = 1.f / (1.f + __expf(-(v0 + b0)));
                    v1 = 1.f / (1.f + __expf(-(v1 + b1)));
                    v2 = 1.f / (1.f + __expf(-(v2 + b0)));
                    v3 = 1.f / (1.f + __expf(-(v3 + b1)));
                }
                if (col + 1 < nstore) {
                    *(float2*)&C[(size_t)r0 * ldc + col]       = make_float2(v0, v1);
                    *(float2*)&C[(size_t)(r0 + 8) * ldc + col] = make_float2(v2, v3);
                } else {
                    C[(size_t)r0 * ldc + col]       = v0;
                    C[(size_t)(r0 + 8) * ldc + col] = v2;
                }
            }
        }
    }
}

// ---------------------------------------------------------------------------
// Prep kernels
// ---------------------------------------------------------------------------
__global__ void prep_x_kernel(const float* __restrict__ X) {
    int idx = blockIdx.x * blockDim.x + threadIdx.x;   // over 8192*2048/4
    if (idx >= BATCH * IN_DIM / 4) return;
    float4 v = ((const float4*)X)[idx];
    __half2 h0 = __floats2half2_rn(v.x, v.y);
    __half2 h1 = __floats2half2_rn(v.z, v.w);
    ((__half2*)g_Xh)[idx * 2]     = h0;
    ((__half2*)g_Xh)[idx * 2 + 1] = h1;
}

// g_Bih[n][k] = fp16(W_inner[n][k+1]); bias; zero accumulators
__global__ void prep_winner_kernel(const float* __restrict__ Wi) {
    int idx = blockIdx.x * blockDim.x + threadIdx.x;   // over 1024*2048
    if (idx >= 1024 * 2048) return;
    if (idx < 1024) { g_num[idx] = 0.f; g_den[idx] = 0.f; }
    int n = idx >> 11;
    int k = idx & 2047;
    float v = 0.f;
    if (n < NUM_INNER) v = Wi[(size_t)n * (IN_DIM + 1) + 1 + k];
    g_Bih[idx] = __float2half_rn(v);
    if (k == 0) g_bias[n] = (n < NUM_INNER) ? Wi[(size_t)n * (IN_DIM + 1)] : 0.f;
}

// g_Blh[n][k] = fp16(W_leaf[n][k]) (n<1000 else 0)
__global__ void prep_wleaf_kernel(const float* __restrict__ Wl) {
    int idx = blockIdx.x * blockDim.x + threadIdx.x;   // over 1024*1024
    if (idx >= 1024 * 1024) return;
    int n = idx >> 10;
    int k = idx & 1023;
    float v = (n < OUT_DIM) ? Wl[(size_t)n * NUM_LEAF + k] : 0.f;
    g_Blh[idx] = __float2half_rn(v);
}

// ---------------------------------------------------------------------------
// Cascade: exact mu + all_pp to output; fp16 mu copy into g_Xh for GEMM2.
// ---------------------------------------------------------------------------
__global__ __launch_bounds__(256)
void cascade_kernel(const float* __restrict__ P, float* __restrict__ mu_out,
                    float* __restrict__ allpp)
{
    const int ROWS = 2;
    __shared__ float p_sh[ROWS][1024];
    __shared__ float buf[2][ROWS][1024];

    const int tid = threadIdx.x;
    const int b0 = blockIdx.x * ROWS;

#pragma unroll
    for (int r = 0; r < ROWS; r++)
        for (int j = tid; j < NUM_INNER; j += 256)
            p_sh[r][j] = P[(size_t)(b0 + r) * 1024 + j];

    if (tid < ROWS) {
        buf[0][tid][0] = 1.f;
        allpp[(size_t)(b0 + tid) * ALLPP_COLS + 0] = 1.f;
    }
    __syncthreads();

    int cur = 0;
    for (int lvl = 0; lvl < DEPTH; lvl++) {
        const int n = 1 << lvl;
        const int start = n - 1;
        const int outbase = 2 * n - 1;
        const int total = ROWS * 2 * n;
        for (int idx = tid; idx < total; idx += 256) {
            int r  = idx / (2 * n);
            int jj = idx - r * (2 * n);
            int j  = jj >> 1;
            int cc = jj & 1;
            float pm = p_sh[r][start + j];
            float v  = buf[cur][r][j] * (cc ? pm : (1.f - pm));
            buf[cur ^ 1][r][jj] = v;
            allpp[(size_t)(b0 + r) * ALLPP_COLS + outbase + jj] = v;
            if (lvl == DEPTH - 1) {
                mu_out[(size_t)(b0 + r) * NUM_LEAF + jj] = v;
                g_Xh[(size_t)(b0 + r) * 1024 + jj] = __float2half_rn(v);
            }
        }
        __syncthreads();
        cur ^= 1;
    }
}

// ---------------------------------------------------------------------------
// Penalty
// ---------------------------------------------------------------------------
__global__ __launch_bounds__(256)
void pen_accum_kernel(const float* __restrict__ P, const float* __restrict__ allpp)
{
    __shared__ float s_num[NUM_INNER];
    __shared__ float s_den[NUM_INNER];
    const int tid = threadIdx.x;
    for (int k = tid; k < NUM_INNER; k += 256) { s_num[k] = 0.f; s_den[k] = 0.f; }
    __syncthreads();

    const int rows_per_block = BATCH / gridDim.x;
    const int b0 = blockIdx.x * rows_per_block;
    for (int b = b0; b < b0 + rows_per_block; b++) {
        const float* mu_row = allpp + (size_t)b * ALLPP_COLS;
        const float* p_row  = P + (size_t)b * 1024;
        for (int k = tid; k < NUM_INNER; k += 256) {
            float m = mu_row[k];
            s_num[k] += p_row[k] * m;
            s_den[k] += m;
        }
    }
    __syncthreads();
    for (int k = tid; k < NUM_INNER; k += 256) {
        atomicAdd(&g_num[k], s_num[k]);
        atomicAdd(&g_den[k], s_den[k]);
    }
}

__global__ __launch_bounds__(256)
void pen_final_kernel(float* __restrict__ pen_out)
{
    __shared__ float red[256];
    const int tid = threadIdx.x;
    float local = 0.f;
    for (int k = tid; k < NUM_INNER; k += 256) {
        float alpha = g_num[k] / g_den[k];
        float pen = logf(alpha) + logf(1.f - alpha);
        if (!isfinite(pen)) pen = 0.f;
        int lvl = 31 - __clz(k + 1);
        float w = ldexpf(0.5f, -lvl);
        local -= w * pen;
    }
    red[tid] = local;
    __syncthreads();
    for (int s = 128; s > 0; s >>= 1) {
        if (tid < s) red[tid] += red[tid + s];
        __syncthreads();
    }
    if (tid == 0) pen_out[0] = red[0];
}

// ---------------------------------------------------------------------------
// Launch
// ---------------------------------------------------------------------------
extern "C" void kernel_launch(void* const* d_in, const int* in_sizes, int n_in,
                              void* d_out, int out_size)
{
    const float* X  = (const float*)d_in[0];
    const float* Wi = (const float*)d_in[1];
    const float* Wl = (const float*)d_in[2];
    float* out = (float*)d_out;

    float* logits = out + LOGITS_OFF;
    float* mu     = out + MU_OFF;
    float* pen    = out + PEN_OFF;
    float* allpp  = out + ALLPP_OFF;

    __half* Xh = nullptr;
    float*  P  = nullptr;
    __half* Bi = nullptr;
    __half* Bl = nullptr;
    cudaGetSymbolAddress((void**)&Xh, g_Xh);
    cudaGetSymbolAddress((void**)&P,  g_P);
    cudaGetSymbolAddress((void**)&Bi, g_Bih);
    cudaGetSymbolAddress((void**)&Bl, g_Blh);

    cudaFuncSetAttribute(mgemm<true>,
                         cudaFuncAttributeMaxDynamicSharedMemorySize, GEMM_SMEM);
    cudaFuncSetAttribute(mgemm<false>,
                         cudaFuncAttributeMaxDynamicSharedMemorySize, GEMM_SMEM);

    prep_x_kernel<<<(BATCH * IN_DIM / 4 + 255) / 256, 256>>>(X);
    prep_winner_kernel<<<(1024 * 2048 + 255) / 256, 256>>>(Wi);
    prep_wleaf_kernel<<<(1024 * 1024 + 255) / 256, 256>>>(Wl);

    // GEMM1: P = sigmoid(bias + Xh @ g_Bih^T)   [8192 x 1024], K=2048
    {
        dim3 grid(1024 / BN, BATCH / BM);
        mgemm<true><<<grid, 256, GEMM_SMEM>>>(
            Xh, IN_DIM, Bi, IN_DIM, P, 1024, 1024, IN_DIM);
    }

    cascade_kernel<<<BATCH / 2, 256>>>(P, mu, allpp);

    pen_accum_kernel<<<256, 256>>>(P, allpp);
    pen_final_kernel<<<1, 256>>>(pen);

    // GEMM2: logits = mu_h @ g_Blh^T   [8192 x 1000], K=1024
    {
        dim3 grid(1024 / BN, BATCH / BM);
        mgemm<false><<<grid, 256, GEMM_SMEM>>>(
            Xh, NUM_LEAF, Bl, NUM_LEAF, logits, OUT_DIM, OUT_DIM, NUM_LEAF);
    }
}